// round 4
// baseline (speedup 1.0000x reference)
#include <cuda_runtime.h>
#include <cuda_fp16.h>
#include <cstdint>

#define D    256
#define N0c  200000
#define N1c  40000
#define N2c  8000
#define E1c  1000000
#define E2c  200000

// ---- scratch (no allocations allowed) ----
__device__ __half g_nodesh[(size_t)N0c * D];   // fp16 node table (102 MB)
__device__ __half g_h1h[(size_t)N1c * D];      // fp16 h1 for layer-2 gather
__device__ float g_mean1[N1c * D];
__device__ float g_h1[N1c * D];
__device__ float g_mean2[N2c * D];
__device__ int g_cnt1[N1c];
__device__ int g_start1[N1c];
__device__ int g_cur1[N1c];
__device__ int g_cnt2[N2c];
__device__ int g_start2[N2c];
__device__ int g_cur2[N2c];
__device__ int g_ss1[E1c];
__device__ int g_ss2[E2c];

// ---- zero ints ----
__global__ void k_zero_i(int* __restrict__ p, int n) {
    int i = blockIdx.x * blockDim.x + threadIdx.x;
    if (i < n) p[i] = 0;
}

// ---- fp32 -> fp16 conversion, 8 floats / thread ----
__global__ void k_cvt(const float4* __restrict__ in, uint4* __restrict__ out, int n8) {
    int i = blockIdx.x * blockDim.x + threadIdx.x;
    int stride = gridDim.x * blockDim.x;
    for (; i < n8; i += stride) {
        float4 a = __ldg(in + 2 * i);
        float4 b = __ldg(in + 2 * i + 1);
        __half2 h[4];
        h[0] = __floats2half2_rn(a.x, a.y);
        h[1] = __floats2half2_rn(a.z, a.w);
        h[2] = __floats2half2_rn(b.x, b.y);
        h[3] = __floats2half2_rn(b.z, b.w);
        out[i] = *reinterpret_cast<uint4*>(h);
    }
}

// ---- histogram of dst ----
__global__ void k_hist(const int* __restrict__ dst, int* __restrict__ cnt, int ne) {
    int i = blockIdx.x * blockDim.x + threadIdx.x;
    int stride = gridDim.x * blockDim.x;
    for (; i < ne; i += stride) atomicAdd(&cnt[dst[i]], 1);
}

// ---- single-block exclusive scan ----
__global__ void k_scan(const int* __restrict__ cnt, int* __restrict__ start,
                       int* __restrict__ cursor, int n) {
    __shared__ int sh[32];
    __shared__ int carry;
    const int tid = threadIdx.x;
    if (tid == 0) carry = 0;
    __syncthreads();
    for (int base = 0; base < n; base += 1024) {
        const int i = base + tid;
        const int v = (i < n) ? cnt[i] : 0;
        int x = v;
#pragma unroll
        for (int o = 1; o < 32; o <<= 1) {
            int y = __shfl_up_sync(~0u, x, o);
            if ((tid & 31) >= o) x += y;
        }
        if ((tid & 31) == 31) sh[tid >> 5] = x;
        __syncthreads();
        if (tid < 32) {
            int s = sh[tid];
#pragma unroll
            for (int o = 1; o < 32; o <<= 1) {
                int y = __shfl_up_sync(~0u, s, o);
                if (tid >= o) s += y;
            }
            sh[tid] = s;
        }
        __syncthreads();
        const int wpref = (tid >= 32) ? sh[(tid >> 5) - 1] : 0;
        const int incl = x + wpref;
        const int excl = incl - v + carry;
        if (i < n) { start[i] = excl; cursor[i] = excl; }
        __syncthreads();
        if (tid == 0) carry += sh[31];
        __syncthreads();
    }
}

// ---- bucket-scatter src ids into dst-sorted order ----
__global__ void k_sidx(const int* __restrict__ src, const int* __restrict__ dst,
                       int* __restrict__ cursor, int* __restrict__ ss, int ne) {
    int i = blockIdx.x * blockDim.x + threadIdx.x;
    int stride = gridDim.x * blockDim.x;
    for (; i < ne; i += stride) {
        int d = dst[i];
        int p = atomicAdd(&cursor[d], 1);
        ss[p] = src[i];
    }
}

// ---- gather-aggregate from fp16 table: one warp per dst node, writes fp32 MEAN ----
__global__ __launch_bounds__(256) void k_gather_h(
    const __half* __restrict__ x, const int* __restrict__ ss,
    const int* __restrict__ start, const int* __restrict__ cnt,
    float* __restrict__ mean, int n)
{
    int w = (blockIdx.x * blockDim.x + threadIdx.x) >> 5;
    if (w >= n) return;
    const int lane = threadIdx.x & 31;
    const int beg = __ldg(start + w);
    const int c = __ldg(cnt + w);
    const int end = beg + c;

    float acc[8];
#pragma unroll
    for (int j = 0; j < 8; j++) acc[j] = 0.f;

    int i = beg;
    for (; i + 2 <= end; i += 2) {
        const int s0 = __ldg(ss + i);
        const int s1 = __ldg(ss + i + 1);
        uint4 v0 = __ldg(reinterpret_cast<const uint4*>(x + (size_t)s0 * D) + lane);
        uint4 v1 = __ldg(reinterpret_cast<const uint4*>(x + (size_t)s1 * D) + lane);
        const __half2* p0 = reinterpret_cast<const __half2*>(&v0);
        const __half2* p1 = reinterpret_cast<const __half2*>(&v1);
#pragma unroll
        for (int j = 0; j < 4; j++) {
            float2 f0 = __half22float2(p0[j]);
            float2 f1 = __half22float2(p1[j]);
            acc[2 * j]     += f0.x + f1.x;
            acc[2 * j + 1] += f0.y + f1.y;
        }
    }
    if (i < end) {
        const int s0 = __ldg(ss + i);
        uint4 v0 = __ldg(reinterpret_cast<const uint4*>(x + (size_t)s0 * D) + lane);
        const __half2* p0 = reinterpret_cast<const __half2*>(&v0);
#pragma unroll
        for (int j = 0; j < 4; j++) {
            float2 f0 = __half22float2(p0[j]);
            acc[2 * j]     += f0.x;
            acc[2 * j + 1] += f0.y;
        }
    }
    const float inv = 1.0f / fmaxf((float)c, 1.0f);
    float4 w0 = make_float4(acc[0] * inv, acc[1] * inv, acc[2] * inv, acc[3] * inv);
    float4 w1 = make_float4(acc[4] * inv, acc[5] * inv, acc[6] * inv, acc[7] * inv);
    float4* mr = reinterpret_cast<float4*>(mean + (size_t)w * D);
    mr[2 * lane]     = w0;
    mr[2 * lane + 1] = w1;
}

// ---- tf32 helpers ----
__device__ __forceinline__ uint32_t f2tf(float f) {
    uint32_t u;
    asm("cvt.rna.tf32.f32 %0, %1;" : "=r"(u) : "f"(f));
    return u;
}

__device__ __forceinline__ void mma_tf32(float c[4], const uint32_t a[4], const uint32_t b[2]) {
    asm volatile(
        "mma.sync.aligned.m16n8k8.row.col.f32.tf32.tf32.f32 "
        "{%0,%1,%2,%3}, {%4,%5,%6,%7}, {%8,%9}, {%0,%1,%2,%3};"
        : "+f"(c[0]), "+f"(c[1]), "+f"(c[2]), "+f"(c[3])
        : "r"(a[0]), "r"(a[1]), "r"(a[2]), "r"(a[3]), "r"(b[0]), "r"(b[1]));
}

// ---- fused SAGE layer GEMM (tf32 tensor cores), optional fp16 secondary output ----
__global__ __launch_bounds__(256) void k_sage_mma(
    const float* __restrict__ mean,
    const float* __restrict__ xt, const float* __restrict__ Wl,
    const float* __restrict__ Wr, const float* __restrict__ bias,
    float* __restrict__ out, __half* __restrict__ out_h, int M)
{
    __shared__ uint32_t As[128][20];
    __shared__ uint32_t Bs[128][20];

    const int m0 = blockIdx.x * 128;
    const int n0 = blockIdx.y * 128;
    const int t  = threadIdx.x;

    const int lrow = t >> 1;
    const int half = t & 1;
    const int gm   = m0 + lrow;
    const bool mval = gm < M;
    const float* mrow = mean + (size_t)gm * D;
    const float* xrow = xt  + (size_t)gm * D;
    const int gj = n0 + lrow;

    const int warp = t >> 5;
    const int lane = t & 31;
    const int gid  = lane >> 2;
    const int tig  = lane & 3;
    const int wm0  = (warp & 1) * 64;
    const int wn0  = (warp >> 1) * 32;

    float acc[4][4][4];
#pragma unroll
    for (int mf = 0; mf < 4; mf++)
#pragma unroll
        for (int nf = 0; nf < 4; nf++)
#pragma unroll
            for (int r = 0; r < 4; r++) acc[mf][nf][r] = 0.f;

    for (int kt = 0; kt < 32; kt++) {
        const int k0 = kt * 16;
        const bool in_agg = (k0 < 256);
        const int kk0 = in_agg ? k0 : (k0 - 256);

        float4 a0 = make_float4(0.f, 0.f, 0.f, 0.f), a1 = a0;
        if (mval) {
            const float* sp = (in_agg ? mrow : xrow) + kk0 + half * 8;
            a0 = *reinterpret_cast<const float4*>(sp);
            a1 = *reinterpret_cast<const float4*>(sp + 4);
        }
        const float* W  = in_agg ? Wl : Wr;
        const float* bp = W + (size_t)gj * D + kk0 + half * 8;
        float4 b0v = *reinterpret_cast<const float4*>(bp);
        float4 b1v = *reinterpret_cast<const float4*>(bp + 4);

        __syncthreads();
        {
            const int kb = half * 8;
            As[lrow][kb + 0] = f2tf(a0.x); As[lrow][kb + 1] = f2tf(a0.y);
            As[lrow][kb + 2] = f2tf(a0.z); As[lrow][kb + 3] = f2tf(a0.w);
            As[lrow][kb + 4] = f2tf(a1.x); As[lrow][kb + 5] = f2tf(a1.y);
            As[lrow][kb + 6] = f2tf(a1.z); As[lrow][kb + 7] = f2tf(a1.w);
            Bs[lrow][kb + 0] = f2tf(b0v.x); Bs[lrow][kb + 1] = f2tf(b0v.y);
            Bs[lrow][kb + 2] = f2tf(b0v.z); Bs[lrow][kb + 3] = f2tf(b0v.w);
            Bs[lrow][kb + 4] = f2tf(b1v.x); Bs[lrow][kb + 5] = f2tf(b1v.y);
            Bs[lrow][kb + 6] = f2tf(b1v.z); Bs[lrow][kb + 7] = f2tf(b1v.w);
        }
        __syncthreads();

#pragma unroll
        for (int k8 = 0; k8 < 2; k8++) {
            const int kb2 = k8 * 8;
            uint32_t af[4][4], bf[4][2];
#pragma unroll
            for (int mf = 0; mf < 4; mf++) {
                const int r = wm0 + mf * 16 + gid;
                af[mf][0] = As[r][kb2 + tig];
                af[mf][1] = As[r + 8][kb2 + tig];
                af[mf][2] = As[r][kb2 + tig + 4];
                af[mf][3] = As[r + 8][kb2 + tig + 4];
            }
#pragma unroll
            for (int nf = 0; nf < 4; nf++) {
                const int c = wn0 + nf * 8 + gid;
                bf[nf][0] = Bs[c][kb2 + tig];
                bf[nf][1] = Bs[c][kb2 + tig + 4];
            }
#pragma unroll
            for (int mf = 0; mf < 4; mf++)
#pragma unroll
                for (int nf = 0; nf < 4; nf++)
                    mma_tf32(acc[mf][nf], af[mf], bf[nf]);
        }
    }

#pragma unroll
    for (int nf = 0; nf < 4; nf++) {
        const int cb = n0 + wn0 + nf * 8 + tig * 2;
        const float bx = __ldg(bias + cb);
        const float by = __ldg(bias + cb + 1);
#pragma unroll
        for (int mf = 0; mf < 4; mf++) {
            const int r0 = m0 + wm0 + mf * 16 + gid;
            if (r0 < M) {
                float2 v;
                v.x = tanhf(acc[mf][nf][0] + bx);
                v.y = tanhf(acc[mf][nf][1] + by);
                *reinterpret_cast<float2*>(out + (size_t)r0 * D + cb) = v;
                if (out_h)
                    *reinterpret_cast<__half2*>(out_h + (size_t)r0 * D + cb) =
                        __floats2half2_rn(v.x, v.y);
            }
            const int r1 = r0 + 8;
            if (r1 < M) {
                float2 v;
                v.x = tanhf(acc[mf][nf][2] + bx);
                v.y = tanhf(acc[mf][nf][3] + by);
                *reinterpret_cast<float2*>(out + (size_t)r1 * D + cb) = v;
                if (out_h)
                    *reinterpret_cast<__half2*>(out_h + (size_t)r1 * D + cb) =
                        __floats2half2_rn(v.x, v.y);
            }
        }
    }
}

extern "C" void kernel_launch(void* const* d_in, const int* in_sizes, int n_in,
                              void* d_out, int out_size) {
    const float* nodes = (const float*)d_in[0];
    const float* W_l1  = (const float*)d_in[1];
    const float* b1    = (const float*)d_in[2];
    const float* W_r1  = (const float*)d_in[3];
    const float* W_l2  = (const float*)d_in[4];
    const float* b2    = (const float*)d_in[5];
    const float* W_r2  = (const float*)d_in[6];
    const int*   src1  = (const int*)d_in[7];
    const int*   dst1  = (const int*)d_in[8];
    const int*   src2  = (const int*)d_in[9];
    const int*   dst2  = (const int*)d_in[10];
    float* out = (float*)d_out;

    float *mean1, *h1, *mean2;
    __half *nodesh, *h1h;
    int *cnt1, *start1, *cur1, *cnt2, *start2, *cur2, *ss1, *ss2;
    cudaGetSymbolAddress((void**)&nodesh, g_nodesh);
    cudaGetSymbolAddress((void**)&h1h,    g_h1h);
    cudaGetSymbolAddress((void**)&mean1,  g_mean1);
    cudaGetSymbolAddress((void**)&h1,     g_h1);
    cudaGetSymbolAddress((void**)&mean2,  g_mean2);
    cudaGetSymbolAddress((void**)&cnt1,   g_cnt1);
    cudaGetSymbolAddress((void**)&start1, g_start1);
    cudaGetSymbolAddress((void**)&cur1,   g_cur1);
    cudaGetSymbolAddress((void**)&cnt2,   g_cnt2);
    cudaGetSymbolAddress((void**)&start2, g_start2);
    cudaGetSymbolAddress((void**)&cur2,   g_cur2);
    cudaGetSymbolAddress((void**)&ss1,    g_ss1);
    cudaGetSymbolAddress((void**)&ss2,    g_ss2);

    // fp16 node table
    {
        int n8 = (int)(((size_t)N0c * D) / 8);
        k_cvt<<<2368, 256>>>((const float4*)nodes, (uint4*)nodesh, n8);
    }

    // ---- layer 1 ----
    k_zero_i<<<(N1c + 255) / 256, 256>>>(cnt1, N1c);
    k_hist<<<592, 256>>>(dst1, cnt1, E1c);
    k_scan<<<1, 1024>>>(cnt1, start1, cur1, N1c);
    k_sidx<<<592, 256>>>(src1, dst1, cur1, ss1, E1c);
    k_gather_h<<<(N1c * 32 + 255) / 256, 256>>>(nodesh, ss1, start1, cnt1, mean1, N1c);
    {
        dim3 grid((N1c + 127) / 128, 2);
        k_sage_mma<<<grid, 256>>>(mean1, nodes, W_l1, W_r1, b1, h1, h1h, N1c);
    }

    // ---- layer 2 ----
    k_zero_i<<<(N2c + 255) / 256, 256>>>(cnt2, N2c);
    k_hist<<<592, 256>>>(dst2, cnt2, E2c);
    k_scan<<<1, 1024>>>(cnt2, start2, cur2, N2c);
    k_sidx<<<592, 256>>>(src2, dst2, cur2, ss2, E2c);
    k_gather_h<<<(N2c * 32 + 255) / 256, 256>>>(h1h, ss2, start2, cnt2, mean2, N2c);
    {
        dim3 grid((N2c + 127) / 128, 2);
        k_sage_mma<<<grid, 256>>>(mean2, h1, W_l2, W_r2, b2, out, ((__half*)0), N2c);
    }
}